// round 7
// baseline (speedup 1.0000x reference)
#include <cuda_runtime.h>

#define N 384
#define N2 (2 * N)
#define D 256
#define EPSF 1e-12f
#define NTILES 21
#define NUNITS (NTILES * N)   // 8064
#define NBLK 296

typedef unsigned long long u64;

// scratch (no allocation allowed)
__device__ float  g_Gs[N * N];
__device__ float  g_Gt[N * N];
__device__ float  g_ps[N * N];      // p = inv_ij          (j-side, plain)
__device__ float  g_cps[N * N];     // (G_ii - G_ij) * p   (j-side, plain)
__device__ float  g_psd[N * N2];    // {p,p} duplicated     (k-side)
__device__ float  g_nrd[N * N2];    // {-G_ij*p, dup}       (k-side)
__device__ float  g_pt[N * N];
__device__ float  g_cpt[N * N];
__device__ float  g_ptd[N * N2];
__device__ float  g_ntd[N * N2];
__device__ double g_sum;
__device__ int    g_cnt;

// upper-triangle 64x64 tile enumeration (a <= b), 21 tiles over a 6x6 grid
__constant__ int c_TA[NTILES] = {0,0,0,0,0,0,1,1,1,1,1,2,2,2,2,3,3,3,4,4,5};
__constant__ int c_TB[NTILES] = {0,1,2,3,4,5,1,2,3,4,5,2,3,4,5,3,4,5,4,5,5};

// ---------------------------------------------------------------------------
// packed f32x2 helpers (sm_103a)
__device__ __forceinline__ u64 pack2(float lo, float hi) {
    u64 r; asm("mov.b64 %0,{%1,%2};" : "=l"(r) : "f"(lo), "f"(hi)); return r;
}
__device__ __forceinline__ float2 unpack2(u64 v) {
    float2 f; asm("mov.b64 {%0,%1},%2;" : "=f"(f.x), "=f"(f.y) : "l"(v)); return f;
}
__device__ __forceinline__ u64 mul2(u64 a, u64 b) {
    u64 r; asm("mul.rn.f32x2 %0,%1,%2;" : "=l"(r) : "l"(a), "l"(b)); return r;
}
__device__ __forceinline__ u64 fma2(u64 a, u64 b, u64 c) {
    u64 r; asm("fma.rn.f32x2 %0,%1,%2,%3;" : "=l"(r) : "l"(a), "l"(b), "l"(c)); return r;
}

// ---------------------------------------------------------------------------
// Fused Gram + prep with double-buffered smem (1 sync per 32-k chunk).
// Epilogue emits G, plain j-side arrays (p, cp) and duplicated k-side arrays.
// grid (6, 12, 2), 256 threads, 2x4 microtile.
__global__ void __launch_bounds__(256) rkd_gram_prep_kernel(const float* __restrict__ S,
                                                            const float* __restrict__ T) {
    const float* __restrict__ E = (blockIdx.z == 0) ? S : T;
    float* __restrict__ G  = (blockIdx.z == 0) ? g_Gs  : g_Gt;
    float* __restrict__ P  = (blockIdx.z == 0) ? g_ps  : g_pt;
    float* __restrict__ CP = (blockIdx.z == 0) ? g_cps : g_cpt;
    float* __restrict__ PD = (blockIdx.z == 0) ? g_psd : g_ptd;
    float* __restrict__ ND = (blockIdx.z == 0) ? g_nrd : g_ntd;

    __shared__ float As[2][32][34];   // [buf][kc][j]
    __shared__ float Bs[2][32][68];   // [buf][kc][k]
    __shared__ float dA[32];          // diag of j rows
    __shared__ float dB[64];          // diag of k rows

    int tid = threadIdx.x;
    if (blockIdx.x == 0 && blockIdx.y == 0 && blockIdx.z == 0 && tid == 0) {
        g_sum = 0.0; g_cnt = 0;
    }

    int ty = tid >> 4, tx = tid & 15;      // ty: j-pair 0..15, tx: k-quad 0..15
    int row = tid >> 3;                    // 0..31
    int c4 = (tid & 7) * 4;                // 0..28

    int tj = blockIdx.y * 32, tk = blockIdx.x * 64;

    const float* pA  = &E[(tj + row) * D + c4];
    const float* pB0 = &E[(tk + row) * D + c4];
    const float* pB1 = &E[(tk + 32 + row) * D + c4];

    float acc[2][4];
#pragma unroll
    for (int r = 0; r < 2; r++)
#pragma unroll
        for (int c = 0; c < 4; c++) acc[r][c] = 0.f;

    float ssA = 0.f, ssB0 = 0.f, ssB1 = 0.f;

    // prologue: load chunk 0 into buf 0
    float4 av  = *reinterpret_cast<const float4*>(pA);
    float4 bv0 = *reinterpret_cast<const float4*>(pB0);
    float4 bv1 = *reinterpret_cast<const float4*>(pB1);
    As[0][c4 + 0][row] = av.x;  As[0][c4 + 1][row] = av.y;
    As[0][c4 + 2][row] = av.z;  As[0][c4 + 3][row] = av.w;
    Bs[0][c4 + 0][row] = bv0.x; Bs[0][c4 + 1][row] = bv0.y;
    Bs[0][c4 + 2][row] = bv0.z; Bs[0][c4 + 3][row] = bv0.w;
    Bs[0][c4 + 0][row + 32] = bv1.x; Bs[0][c4 + 1][row + 32] = bv1.y;
    Bs[0][c4 + 2][row + 32] = bv1.z; Bs[0][c4 + 3][row + 32] = bv1.w;
    ssA  = fmaf(av.x,  av.x,  fmaf(av.y,  av.y,  fmaf(av.z,  av.z,  fmaf(av.w,  av.w,  ssA))));
    ssB0 = fmaf(bv0.x, bv0.x, fmaf(bv0.y, bv0.y, fmaf(bv0.z, bv0.z, fmaf(bv0.w, bv0.w, ssB0))));
    ssB1 = fmaf(bv1.x, bv1.x, fmaf(bv1.y, bv1.y, fmaf(bv1.z, bv1.z, fmaf(bv1.w, bv1.w, ssB1))));
    __syncthreads();

#pragma unroll
    for (int chunk = 0; chunk < D / 32; chunk++) {
        int cur = chunk & 1;
        bool more = (chunk < D / 32 - 1);
        if (more) {
            int off = (chunk + 1) * 32;
            av  = *reinterpret_cast<const float4*>(pA  + off);
            bv0 = *reinterpret_cast<const float4*>(pB0 + off);
            bv1 = *reinterpret_cast<const float4*>(pB1 + off);
        }
#pragma unroll
        for (int kk = 0; kk < 32; kk++) {
            float2 a2 = *reinterpret_cast<const float2*>(&As[cur][kk][ty * 2]);
            float4 b4 = *reinterpret_cast<const float4*>(&Bs[cur][kk][tx * 4]);
            acc[0][0] = fmaf(a2.x, b4.x, acc[0][0]);
            acc[0][1] = fmaf(a2.x, b4.y, acc[0][1]);
            acc[0][2] = fmaf(a2.x, b4.z, acc[0][2]);
            acc[0][3] = fmaf(a2.x, b4.w, acc[0][3]);
            acc[1][0] = fmaf(a2.y, b4.x, acc[1][0]);
            acc[1][1] = fmaf(a2.y, b4.y, acc[1][1]);
            acc[1][2] = fmaf(a2.y, b4.z, acc[1][2]);
            acc[1][3] = fmaf(a2.y, b4.w, acc[1][3]);
        }
        if (more) {
            int nb = cur ^ 1;
            As[nb][c4 + 0][row] = av.x;  As[nb][c4 + 1][row] = av.y;
            As[nb][c4 + 2][row] = av.z;  As[nb][c4 + 3][row] = av.w;
            Bs[nb][c4 + 0][row] = bv0.x; Bs[nb][c4 + 1][row] = bv0.y;
            Bs[nb][c4 + 2][row] = bv0.z; Bs[nb][c4 + 3][row] = bv0.w;
            Bs[nb][c4 + 0][row + 32] = bv1.x; Bs[nb][c4 + 1][row + 32] = bv1.y;
            Bs[nb][c4 + 2][row + 32] = bv1.z; Bs[nb][c4 + 3][row + 32] = bv1.w;
            ssA  = fmaf(av.x,  av.x,  fmaf(av.y,  av.y,  fmaf(av.z,  av.z,  fmaf(av.w,  av.w,  ssA))));
            ssB0 = fmaf(bv0.x, bv0.x, fmaf(bv0.y, bv0.y, fmaf(bv0.z, bv0.z, fmaf(bv0.w, bv0.w, ssB0))));
            ssB1 = fmaf(bv1.x, bv1.x, fmaf(bv1.y, bv1.y, fmaf(bv1.z, bv1.z, fmaf(bv1.w, bv1.w, ssB1))));
        }
        __syncthreads();
    }

    // reduce sum-of-squares over the 8 lanes sharing a row (contiguous lanes)
#pragma unroll
    for (int m = 4; m > 0; m >>= 1) {
        ssA  += __shfl_xor_sync(0xffffffffu, ssA,  m, 8);
        ssB0 += __shfl_xor_sync(0xffffffffu, ssB0, m, 8);
        ssB1 += __shfl_xor_sync(0xffffffffu, ssB1, m, 8);
    }
    if ((tid & 7) == 0) {
        dA[row] = ssA;
        dB[row] = ssB0;
        dB[row + 32] = ssB1;
    }
    __syncthreads();

    int jg = tj + ty * 2;
    int kg = tk + tx * 4;
#pragma unroll
    for (int r = 0; r < 2; r++) {
        int ig = jg + r;
        float di = dA[ty * 2 + r];

        float p[4], cp[4], nr[4];
#pragma unroll
        for (int c = 0; c < 4; c++) {
            float gij = acc[r][c];
            float dj = dB[tx * 4 + c];
            float cs = di - gij;
            float n2 = fmaxf((dj - gij) + cs, 0.f);
            float pv = (ig == kg + c) ? 0.f : (1.f / fmaxf(sqrtf(n2), EPSF));
            p[c] = pv;
            cp[c] = cs * pv;
            nr[c] = -gij * pv;
        }
        *reinterpret_cast<float4*>(&G[ig * N + kg]) =
            make_float4(acc[r][0], acc[r][1], acc[r][2], acc[r][3]);
        *reinterpret_cast<float4*>(&P[ig * N + kg])  = make_float4(p[0], p[1], p[2], p[3]);
        *reinterpret_cast<float4*>(&CP[ig * N + kg]) = make_float4(cp[0], cp[1], cp[2], cp[3]);
        *reinterpret_cast<float4*>(&PD[ig * N2 + 2 * kg])     = make_float4(p[0], p[0], p[1], p[1]);
        *reinterpret_cast<float4*>(&PD[ig * N2 + 2 * kg + 4]) = make_float4(p[2], p[2], p[3], p[3]);
        *reinterpret_cast<float4*>(&ND[ig * N2 + 2 * kg])     = make_float4(nr[0], nr[0], nr[1], nr[1]);
        *reinterpret_cast<float4*>(&ND[ig * N2 + 2 * kg + 4]) = make_float4(nr[2], nr[2], nr[3], nr[3]);
    }
}

// ---------------------------------------------------------------------------
// Main: balanced flatten of 8064 (tile, i) units over exactly NBLK blocks.
// Packed along j: pairs {j0,j1},{j2,j3}. j-side p/cp load as natural u64
// pairs; k-side q/nr load as pre-duplicated broadcast pairs. Zero pack movs.
//   angle = q_k*(p_j*G_jk + cp_j) + nr_k*p_j
__global__ void __launch_bounds__(256, 2) rkd_angle_loss_kernel(float* __restrict__ out) {
    int tid = threadIdx.x;
    int ty = tid >> 4, tx = tid & 15;
    int b = blockIdx.x;

    int u0 = (b * NUNITS) / NBLK;
    int u1 = ((b + 1) * NUNITS) / NBLK;
    int tile = u0 / N;
    int i = u0 - tile * N;
    int remaining = u1 - u0;

    const u64 NEG1 = 0xBF800000BF800000ULL;  // {-1.f, -1.f}

    float wacc = 0.f;

    while (remaining > 0) {
        int cnt = min(N - i, remaining);
        remaining -= cnt;

        int jq = c_TA[tile] * 64 + ty * 4;
        int kq = c_TB[tile] * 64 + tx * 4;

        // G microtile packed along j: G2[k][jp] = {G[jq+2jp][k], G[jq+2jp+1][k]}
        u64 G2s[4][2], G2t[4][2];
        {
            float4 vs[4], vt[4];
#pragma unroll
            for (int jj = 0; jj < 4; jj++) {
                vs[jj] = *reinterpret_cast<const float4*>(&g_Gs[(jq + jj) * N + kq]);
                vt[jj] = *reinterpret_cast<const float4*>(&g_Gt[(jq + jj) * N + kq]);
            }
            const float* s0 = &vs[0].x; const float* s1 = &vs[1].x;
            const float* s2 = &vs[2].x; const float* s3 = &vs[3].x;
            const float* t0 = &vt[0].x; const float* t1 = &vt[1].x;
            const float* t2 = &vt[2].x; const float* t3 = &vt[3].x;
#pragma unroll
            for (int k = 0; k < 4; k++) {
                G2s[k][0] = pack2(s0[k], s1[k]);
                G2s[k][1] = pack2(s2[k], s3[k]);
                G2t[k][0] = pack2(t0[k], t1[k]);
                G2t[k][1] = pack2(t2[k], t3[k]);
            }
        }

        float acc0 = 0.f, acc1 = 0.f;

        for (int s = 0; s < cnt; s++) {
            int base  = (i + s) * N;
            int based = (i + s) * N2;

            // j-side: natural packed pairs (free reinterpret of LDG.128)
            ulonglong2 pjs = *reinterpret_cast<const ulonglong2*>(&g_ps[base + jq]);
            ulonglong2 cjs = *reinterpret_cast<const ulonglong2*>(&g_cps[base + jq]);
            ulonglong2 pjt = *reinterpret_cast<const ulonglong2*>(&g_pt[base + jq]);
            ulonglong2 cjt = *reinterpret_cast<const ulonglong2*>(&g_cpt[base + jq]);

            // k-side: duplicated broadcast pairs
            ulonglong2 qs0 = *reinterpret_cast<const ulonglong2*>(&g_psd[based + 2 * kq]);
            ulonglong2 qs1 = *reinterpret_cast<const ulonglong2*>(&g_psd[based + 2 * kq + 4]);
            ulonglong2 ns0 = *reinterpret_cast<const ulonglong2*>(&g_nrd[based + 2 * kq]);
            ulonglong2 ns1 = *reinterpret_cast<const ulonglong2*>(&g_nrd[based + 2 * kq + 4]);
            ulonglong2 qt0 = *reinterpret_cast<const ulonglong2*>(&g_ptd[based + 2 * kq]);
            ulonglong2 qt1 = *reinterpret_cast<const ulonglong2*>(&g_ptd[based + 2 * kq + 4]);
            ulonglong2 nt0 = *reinterpret_cast<const ulonglong2*>(&g_ntd[based + 2 * kq]);
            ulonglong2 nt1 = *reinterpret_cast<const ulonglong2*>(&g_ntd[based + 2 * kq + 4]);

            u64 q2s[4] = { qs0.x, qs0.y, qs1.x, qs1.y };
            u64 n2s[4] = { ns0.x, ns0.y, ns1.x, ns1.y };
            u64 q2t[4] = { qt0.x, qt0.y, qt1.x, qt1.y };
            u64 n2t[4] = { nt0.x, nt0.y, nt1.x, nt1.y };
            u64 p2s[2] = { pjs.x, pjs.y };
            u64 c2s[2] = { cjs.x, cjs.y };
            u64 p2t[2] = { pjt.x, pjt.y };
            u64 c2t[2] = { cjt.x, cjt.y };

#pragma unroll
            for (int jp = 0; jp < 2; jp++) {
#pragma unroll
                for (int k = 0; k < 4; k++) {
                    u64 t2s = fma2(p2s[jp], G2s[k][jp], c2s[jp]);
                    u64 m2s = mul2(n2s[k], p2s[jp]);
                    u64 a2s = fma2(q2s[k], t2s, m2s);
                    u64 t2t = fma2(p2t[jp], G2t[k][jp], c2t[jp]);
                    u64 m2t = mul2(n2t[k], p2t[jp]);
                    u64 a2t = fma2(q2t[k], t2t, m2t);
                    u64 d2  = fma2(a2t, NEG1, a2s);      // as - at
                    float2 d = unpack2(d2);
                    float x0 = fabsf(d.x), x1 = fabsf(d.y);
                    float y0 = fminf(x0, 1.f), y1 = fminf(x1, 1.f);
                    float t0 = fmaf(y0, -0.5f, x0);
                    float t1 = fmaf(y1, -0.5f, x1);
                    acc0 = fmaf(y0, t0, acc0);
                    acc1 = fmaf(y1, t1, acc1);
                }
            }
        }

        float w = (c_TA[tile] == c_TB[tile]) ? 1.f : 2.f;
        wacc = fmaf(w, acc0 + acc1, wacc);
        tile++;
        i = 0;
    }

    // block reduction
    __shared__ float red[256];
    red[tid] = wacc;
    __syncthreads();
#pragma unroll
    for (int s = 128; s > 0; s >>= 1) {
        if (tid < s) red[tid] += red[tid + s];
        __syncthreads();
    }
    if (tid == 0) {
        atomicAdd(&g_sum, (double)red[0]);
        __threadfence();
        int t = atomicAdd(&g_cnt, 1);
        if (t == NBLK - 1) {
            double v = atomicAdd(&g_sum, 0.0);
            double n3 = (double)N * (double)N * (double)N;
            out[0] = (float)(v / n3);
        }
    }
}

// ---------------------------------------------------------------------------
extern "C" void kernel_launch(void* const* d_in, const int* in_sizes, int n_in,
                              void* d_out, int out_size) {
    const float* student = (const float*)d_in[0];
    const float* teacher = (const float*)d_in[1];
    float* out = (float*)d_out;

    dim3 ggrd(N / 64, N / 32, 2);
    rkd_gram_prep_kernel<<<ggrd, 256>>>(student, teacher);

    rkd_angle_loss_kernel<<<NBLK, 256>>>(out);
}

// round 8
// speedup vs baseline: 1.2697x; 1.2697x over previous
#include <cuda_runtime.h>

#define N 384
#define D 256
#define EPSF 1e-12f
#define NTILES 21
#define NUNITS (NTILES * N)   // 8064
#define NBLK 296
#define BI 8                  // i-batch staged in smem

typedef unsigned long long u64;

// scratch (no allocation allowed)
__device__ float  g_Gs[N * N];
__device__ float  g_Gt[N * N];
__device__ float  g_ps[N * N];     // inv_ij (student)
__device__ float  g_cps[N * N];    // (G_ii - G_ij) * inv_ij
__device__ float  g_nrqs[N * N];   // -G_ij * inv_ij
__device__ float  g_pt[N * N];
__device__ float  g_cpt[N * N];
__device__ float  g_nrqt[N * N];
__device__ double g_sum;
__device__ int    g_cnt;

// upper-triangle 64x64 tile enumeration (a <= b), 21 tiles over a 6x6 grid
__constant__ int c_TA[NTILES] = {0,0,0,0,0,0,1,1,1,1,1,2,2,2,2,3,3,3,4,4,5};
__constant__ int c_TB[NTILES] = {0,1,2,3,4,5,1,2,3,4,5,2,3,4,5,3,4,5,4,5,5};

// ---------------------------------------------------------------------------
// packed f32x2 helpers (sm_103a)
__device__ __forceinline__ u64 pack2(float lo, float hi) {
    u64 r; asm("mov.b64 %0,{%1,%2};" : "=l"(r) : "f"(lo), "f"(hi)); return r;
}
__device__ __forceinline__ float2 unpack2(u64 v) {
    float2 f; asm("mov.b64 {%0,%1},%2;" : "=f"(f.x), "=f"(f.y) : "l"(v)); return f;
}
__device__ __forceinline__ u64 mul2(u64 a, u64 b) {
    u64 r; asm("mul.rn.f32x2 %0,%1,%2;" : "=l"(r) : "l"(a), "l"(b)); return r;
}
__device__ __forceinline__ u64 fma2(u64 a, u64 b, u64 c) {
    u64 r; asm("fma.rn.f32x2 %0,%1,%2,%3;" : "=l"(r) : "l"(a), "l"(b), "l"(c)); return r;
}

// ---------------------------------------------------------------------------
// Fused Gram + prep with double-buffered smem (1 sync per 32-k chunk).
// grid (6, 12, 2), 256 threads, 2x4 microtile.
__global__ void __launch_bounds__(256) rkd_gram_prep_kernel(const float* __restrict__ S,
                                                            const float* __restrict__ T) {
    const float* __restrict__ E = (blockIdx.z == 0) ? S : T;
    float* __restrict__ G  = (blockIdx.z == 0) ? g_Gs   : g_Gt;
    float* __restrict__ P  = (blockIdx.z == 0) ? g_ps   : g_pt;
    float* __restrict__ CP = (blockIdx.z == 0) ? g_cps  : g_cpt;
    float* __restrict__ NR = (blockIdx.z == 0) ? g_nrqs : g_nrqt;

    __shared__ float As[2][32][34];
    __shared__ float Bs[2][32][68];
    __shared__ float dA[32];
    __shared__ float dB[64];

    int tid = threadIdx.x;
    if (blockIdx.x == 0 && blockIdx.y == 0 && blockIdx.z == 0 && tid == 0) {
        g_sum = 0.0; g_cnt = 0;
    }

    int ty = tid >> 4, tx = tid & 15;
    int row = tid >> 3;
    int c4 = (tid & 7) * 4;

    int tj = blockIdx.y * 32, tk = blockIdx.x * 64;

    const float* pA  = &E[(tj + row) * D + c4];
    const float* pB0 = &E[(tk + row) * D + c4];
    const float* pB1 = &E[(tk + 32 + row) * D + c4];

    float acc[2][4];
#pragma unroll
    for (int r = 0; r < 2; r++)
#pragma unroll
        for (int c = 0; c < 4; c++) acc[r][c] = 0.f;

    float ssA = 0.f, ssB0 = 0.f, ssB1 = 0.f;

    float4 av  = *reinterpret_cast<const float4*>(pA);
    float4 bv0 = *reinterpret_cast<const float4*>(pB0);
    float4 bv1 = *reinterpret_cast<const float4*>(pB1);
    As[0][c4 + 0][row] = av.x;  As[0][c4 + 1][row] = av.y;
    As[0][c4 + 2][row] = av.z;  As[0][c4 + 3][row] = av.w;
    Bs[0][c4 + 0][row] = bv0.x; Bs[0][c4 + 1][row] = bv0.y;
    Bs[0][c4 + 2][row] = bv0.z; Bs[0][c4 + 3][row] = bv0.w;
    Bs[0][c4 + 0][row + 32] = bv1.x; Bs[0][c4 + 1][row + 32] = bv1.y;
    Bs[0][c4 + 2][row + 32] = bv1.z; Bs[0][c4 + 3][row + 32] = bv1.w;
    ssA  = fmaf(av.x,  av.x,  fmaf(av.y,  av.y,  fmaf(av.z,  av.z,  fmaf(av.w,  av.w,  ssA))));
    ssB0 = fmaf(bv0.x, bv0.x, fmaf(bv0.y, bv0.y, fmaf(bv0.z, bv0.z, fmaf(bv0.w, bv0.w, ssB0))));
    ssB1 = fmaf(bv1.x, bv1.x, fmaf(bv1.y, bv1.y, fmaf(bv1.z, bv1.z, fmaf(bv1.w, bv1.w, ssB1))));
    __syncthreads();

#pragma unroll
    for (int chunk = 0; chunk < D / 32; chunk++) {
        int cur = chunk & 1;
        bool more = (chunk < D / 32 - 1);
        if (more) {
            int off = (chunk + 1) * 32;
            av  = *reinterpret_cast<const float4*>(pA  + off);
            bv0 = *reinterpret_cast<const float4*>(pB0 + off);
            bv1 = *reinterpret_cast<const float4*>(pB1 + off);
        }
#pragma unroll
        for (int kk = 0; kk < 32; kk++) {
            float2 a2 = *reinterpret_cast<const float2*>(&As[cur][kk][ty * 2]);
            float4 b4 = *reinterpret_cast<const float4*>(&Bs[cur][kk][tx * 4]);
            acc[0][0] = fmaf(a2.x, b4.x, acc[0][0]);
            acc[0][1] = fmaf(a2.x, b4.y, acc[0][1]);
            acc[0][2] = fmaf(a2.x, b4.z, acc[0][2]);
            acc[0][3] = fmaf(a2.x, b4.w, acc[0][3]);
            acc[1][0] = fmaf(a2.y, b4.x, acc[1][0]);
            acc[1][1] = fmaf(a2.y, b4.y, acc[1][1]);
            acc[1][2] = fmaf(a2.y, b4.z, acc[1][2]);
            acc[1][3] = fmaf(a2.y, b4.w, acc[1][3]);
        }
        if (more) {
            int nb = cur ^ 1;
            As[nb][c4 + 0][row] = av.x;  As[nb][c4 + 1][row] = av.y;
            As[nb][c4 + 2][row] = av.z;  As[nb][c4 + 3][row] = av.w;
            Bs[nb][c4 + 0][row] = bv0.x; Bs[nb][c4 + 1][row] = bv0.y;
            Bs[nb][c4 + 2][row] = bv0.z; Bs[nb][c4 + 3][row] = bv0.w;
            Bs[nb][c4 + 0][row + 32] = bv1.x; Bs[nb][c4 + 1][row + 32] = bv1.y;
            Bs[nb][c4 + 2][row + 32] = bv1.z; Bs[nb][c4 + 3][row + 32] = bv1.w;
            ssA  = fmaf(av.x,  av.x,  fmaf(av.y,  av.y,  fmaf(av.z,  av.z,  fmaf(av.w,  av.w,  ssA))));
            ssB0 = fmaf(bv0.x, bv0.x, fmaf(bv0.y, bv0.y, fmaf(bv0.z, bv0.z, fmaf(bv0.w, bv0.w, ssB0))));
            ssB1 = fmaf(bv1.x, bv1.x, fmaf(bv1.y, bv1.y, fmaf(bv1.z, bv1.z, fmaf(bv1.w, bv1.w, ssB1))));
        }
        __syncthreads();
    }

#pragma unroll
    for (int m = 4; m > 0; m >>= 1) {
        ssA  += __shfl_xor_sync(0xffffffffu, ssA,  m, 8);
        ssB0 += __shfl_xor_sync(0xffffffffu, ssB0, m, 8);
        ssB1 += __shfl_xor_sync(0xffffffffu, ssB1, m, 8);
    }
    if ((tid & 7) == 0) {
        dA[row] = ssA;
        dB[row] = ssB0;
        dB[row + 32] = ssB1;
    }
    __syncthreads();

    int jg = tj + ty * 2;
    int kg = tk + tx * 4;
#pragma unroll
    for (int r = 0; r < 2; r++) {
        int ig = jg + r;
        float di = dA[ty * 2 + r];

        float4 pv, cv, nv;
        float* pp = &pv.x; float* cp = &cv.x; float* np = &nv.x;
#pragma unroll
        for (int c = 0; c < 4; c++) {
            float gij = acc[r][c];
            float dj = dB[tx * 4 + c];
            float cs = di - gij;
            float n2 = fmaxf((dj - gij) + cs, 0.f);
            float p = (ig == kg + c) ? 0.f : (1.f / fmaxf(sqrtf(n2), EPSF));
            pp[c] = p;
            cp[c] = cs * p;
            np[c] = -gij * p;
        }
        *reinterpret_cast<float4*>(&G[ig * N + kg]) =
            make_float4(acc[r][0], acc[r][1], acc[r][2], acc[r][3]);
        *reinterpret_cast<float4*>(&P[ig * N + kg])  = pv;
        *reinterpret_cast<float4*>(&CP[ig * N + kg]) = cv;
        *reinterpret_cast<float4*>(&NR[ig * N + kg]) = nv;
    }
}

// ---------------------------------------------------------------------------
// Main: balanced flatten of 8064 (tile, i) units over exactly NBLK blocks.
// Slice data staged in smem in batches of BI anchors: cooperative coalesced
// LDG (0.5 per thread per i) replaces 8 redundant LDG.128 per thread per i.
// Math body identical to R5.  Last block writes out[0].
__global__ void __launch_bounds__(256, 2) rkd_angle_loss_kernel(float* __restrict__ out) {
    // stage[slice][i][off]: slices 0:ps_j 1:cps_j 2:ps_k 3:nrqs_k
    //                              4:pt_j 5:cpt_j 6:pt_k 7:nrqt_k
    __shared__ float stage[8][BI][64];
    __shared__ float red[256];

    int tid = threadIdx.x;
    int ty = tid >> 4, tx = tid & 15;
    int b = blockIdx.x;

    // staging-load decomposition (constant per thread)
    int l_col4 = (tid & 15) * 4;      // float offset within 64-float row
    int l_ii   = (tid >> 4) & 7;      // i within batch
    int l_hi   = tid >> 7;            // 0 or 1: selects even/odd slice

    int u0 = (b * NUNITS) / NBLK;
    int u1 = ((b + 1) * NUNITS) / NBLK;
    int tile = u0 / N;
    int i = u0 - tile * N;
    int remaining = u1 - u0;

    const u64 NEG1 = 0xBF800000BF800000ULL;  // {-1.f, -1.f}

    float wacc = 0.f;

    while (remaining > 0) {
        int cnt = min(N - i, remaining);
        remaining -= cnt;

        int tj = c_TA[tile] * 64;
        int tk = c_TB[tile] * 64;
        int jq = tj + ty * 4;
        int kq = tk + tx * 4;

        // per-tile staging source pointers for this thread's 4 slices
        const float* src0 = (l_hi ? g_cps  + tj : g_ps + tj) + l_col4;   // slice 0/1
        const float* src1 = (l_hi ? g_nrqs + tk : g_ps + tk) + l_col4;   // slice 2/3
        const float* src2 = (l_hi ? g_cpt  + tj : g_pt + tj) + l_col4;   // slice 4/5
        const float* src3 = (l_hi ? g_nrqt + tk : g_pt + tk) + l_col4;   // slice 6/7

        // G microtile (4x4, both sides) in registers as packed pairs
        u64 G2s[4][2], G2t[4][2];
#pragma unroll
        for (int jj = 0; jj < 4; jj++) {
            float4 vs = *reinterpret_cast<const float4*>(&g_Gs[(jq + jj) * N + kq]);
            float4 vt = *reinterpret_cast<const float4*>(&g_Gt[(jq + jj) * N + kq]);
            G2s[jj][0] = pack2(vs.x, vs.y); G2s[jj][1] = pack2(vs.z, vs.w);
            G2t[jj][0] = pack2(vt.x, vt.y); G2t[jj][1] = pack2(vt.z, vt.w);
        }

        float acc0 = 0.f, acc1 = 0.f;

        for (int s = 0; s < cnt; s += BI) {
            // ---- cooperative stage of BI rows (clamped; clamp rows unused) ----
            {
                int ir = min(i + s + l_ii, N - 1) * N;
                float4 v0 = *reinterpret_cast<const float4*>(src0 + ir);
                float4 v1 = *reinterpret_cast<const float4*>(src1 + ir);
                float4 v2 = *reinterpret_cast<const float4*>(src2 + ir);
                float4 v3 = *reinterpret_cast<const float4*>(src3 + ir);
                *reinterpret_cast<float4*>(&stage[0 + l_hi][l_ii][l_col4]) = v0;
                *reinterpret_cast<float4*>(&stage[2 + l_hi][l_ii][l_col4]) = v1;
                *reinterpret_cast<float4*>(&stage[4 + l_hi][l_ii][l_col4]) = v2;
                *reinterpret_cast<float4*>(&stage[6 + l_hi][l_ii][l_col4]) = v3;
            }
            __syncthreads();

            int bi = min(BI, cnt - s);
            for (int ii = 0; ii < bi; ii++) {
                float4 pj_s = *reinterpret_cast<const float4*>(&stage[0][ii][ty * 4]);
                float4 cj_s = *reinterpret_cast<const float4*>(&stage[1][ii][ty * 4]);
                float4 qk_s = *reinterpret_cast<const float4*>(&stage[2][ii][tx * 4]);
                float4 nr_s = *reinterpret_cast<const float4*>(&stage[3][ii][tx * 4]);
                float4 pj_t = *reinterpret_cast<const float4*>(&stage[4][ii][ty * 4]);
                float4 cj_t = *reinterpret_cast<const float4*>(&stage[5][ii][ty * 4]);
                float4 qk_t = *reinterpret_cast<const float4*>(&stage[6][ii][tx * 4]);
                float4 nr_t = *reinterpret_cast<const float4*>(&stage[7][ii][tx * 4]);

                u64 q2s[2] = { pack2(qk_s.x, qk_s.y), pack2(qk_s.z, qk_s.w) };
                u64 n2s[2] = { pack2(nr_s.x, nr_s.y), pack2(nr_s.z, nr_s.w) };
                u64 q2t[2] = { pack2(qk_t.x, qk_t.y), pack2(qk_t.z, qk_t.w) };
                u64 n2t[2] = { pack2(nr_t.x, nr_t.y), pack2(nr_t.z, nr_t.w) };

                float pjs_a[4] = {pj_s.x, pj_s.y, pj_s.z, pj_s.w};
                float cjs_a[4] = {cj_s.x, cj_s.y, cj_s.z, cj_s.w};
                float pjt_a[4] = {pj_t.x, pj_t.y, pj_t.z, pj_t.w};
                float cjt_a[4] = {cj_t.x, cj_t.y, cj_t.z, cj_t.w};

#pragma unroll
                for (int jj = 0; jj < 4; jj++) {
                    u64 p2s = pack2(pjs_a[jj], pjs_a[jj]);
                    u64 c2s = pack2(cjs_a[jj], cjs_a[jj]);
                    u64 p2t = pack2(pjt_a[jj], pjt_a[jj]);
                    u64 c2t = pack2(cjt_a[jj], cjt_a[jj]);
#pragma unroll
                    for (int p = 0; p < 2; p++) {
                        u64 t2s = fma2(p2s, G2s[jj][p], c2s);
                        u64 m2s = mul2(n2s[p], p2s);
                        u64 a2s = fma2(q2s[p], t2s, m2s);
                        u64 t2t = fma2(p2t, G2t[jj][p], c2t);
                        u64 m2t = mul2(n2t[p], p2t);
                        u64 a2t = fma2(q2t[p], t2t, m2t);
                        u64 d2  = fma2(a2t, NEG1, a2s);      // as - at
                        float2 d = unpack2(d2);
                        float x0 = fabsf(d.x), x1 = fabsf(d.y);
                        float y0 = fminf(x0, 1.f), y1 = fminf(x1, 1.f);
                        float t0 = fmaf(y0, -0.5f, x0);
                        float t1 = fmaf(y1, -0.5f, x1);
                        acc0 = fmaf(y0, t0, acc0);
                        acc1 = fmaf(y1, t1, acc1);
                    }
                }
            }
            __syncthreads();
        }

        float w = (c_TA[tile] == c_TB[tile]) ? 1.f : 2.f;
        wacc = fmaf(w, acc0 + acc1, wacc);
        tile++;
        i = 0;
    }

    // block reduction
    red[tid] = wacc;
    __syncthreads();
#pragma unroll
    for (int s = 128; s > 0; s >>= 1) {
        if (tid < s) red[tid] += red[tid + s];
        __syncthreads();
    }
    if (tid == 0) {
        atomicAdd(&g_sum, (double)red[0]);
        __threadfence();
        int t = atomicAdd(&g_cnt, 1);
        if (t == NBLK - 1) {
            double v = atomicAdd(&g_sum, 0.0);
            double n3 = (double)N * (double)N * (double)N;
            out[0] = (float)(v / n3);
        }
    }
}

// ---------------------------------------------------------------------------
extern "C" void kernel_launch(void* const* d_in, const int* in_sizes, int n_in,
                              void* d_out, int out_size) {
    const float* student = (const float*)d_in[0];
    const float* teacher = (const float*)d_in[1];
    float* out = (float*)d_out;

    dim3 ggrd(N / 64, N / 32, 2);
    rkd_gram_prep_kernel<<<ggrd, 256>>>(student, teacher);

    rkd_angle_loss_kernel<<<NBLK, 256>>>(out);
}